// round 13
// baseline (speedup 1.0000x reference)
#include <cuda_runtime.h>
#include <cuda_bf16.h>
#include <math.h>

// Box-embedding conditional-probability loss. B pairs, D=128.
// R13: R10 frame (best 25.1us, ~94% of LTS ceiling) + packed f32x2 math.
// sm_103a FFMA2/FADD2/FMUL2 via PTX *.rn.f32x2 (ptxas never auto-fuses):
// 2 dims per op for all FMA/ADD/MUL work; subs as fma(x, -1, y) packed;
// only FMNMX (join min/max, disjoint min) stays scalar. Even/odd partial
// products stay packed and are combined once at the end. Identical IEEE-RN
// numerics -> rel_err unchanged.

#define EPS_F 1e-8f

typedef unsigned long long u64;

static __device__ __forceinline__ u64 f2_pack(float lo, float hi) {
    u64 r; asm("mov.b64 %0, {%1, %2};" : "=l"(r) : "f"(lo), "f"(hi)); return r;
}
static __device__ __forceinline__ void f2_unpack(u64 v, float& lo, float& hi) {
    asm("mov.b64 {%0, %1}, %2;" : "=f"(lo), "=f"(hi) : "l"(v));
}
static __device__ __forceinline__ u64 f2_fma(u64 a, u64 b, u64 c) {
    u64 r; asm("fma.rn.f32x2 %0, %1, %2, %3;" : "=l"(r) : "l"(a), "l"(b), "l"(c)); return r;
}
static __device__ __forceinline__ u64 f2_add(u64 a, u64 b) {
    u64 r; asm("add.rn.f32x2 %0, %1, %2;" : "=l"(r) : "l"(a), "l"(b)); return r;
}
static __device__ __forceinline__ u64 f2_mul(u64 a, u64 b) {
    u64 r; asm("mul.rn.f32x2 %0, %1, %2;" : "=l"(r) : "l"(a), "l"(b)); return r;
}

static __device__ __forceinline__ float split_mant(float p, int& e) {
    int ib = __float_as_int(p);
    e += ((ib >> 23) & 0xFF) - 127;
    return __int_as_float((ib & 0x007FFFFF) | 0x3F800000);  // [1,2)
}

__global__ void __launch_bounds__(256, 8)
box_pair_kernel(const int* __restrict__ t1x,
                const int* __restrict__ t2x,
                const float* __restrict__ min_tab,
                const float* __restrict__ dlt_tab,
                float* __restrict__ out_pos,
                float* __restrict__ out_neg,
                int B)
{
    const float MIN_MEAN   = (float)((0.0001 + 0.01) / 2.0);
    const float MIN_VAR    = (float)(0.01 - (0.0001 + 0.01) / 2.0);
    const float DELTA_MEAN = (float)((0.9 + 0.999) / 2.0);
    const float DELTA_VAR  = (float)(0.999 - (0.9 + 0.999) / 2.0);

    const u64 MV2 = f2_pack(MIN_VAR,   MIN_VAR);
    const u64 MM2 = f2_pack(MIN_MEAN,  MIN_MEAN);
    const u64 DV2 = f2_pack(DELTA_VAR, DELTA_VAR);
    const u64 DM2 = f2_pack(DELTA_MEAN, DELTA_MEAN);
    const u64 N12 = f2_pack(-1.0f, -1.0f);

    int gtid = blockIdx.x * blockDim.x + threadIdx.x;
    int pair = gtid >> 3;           // 8 lanes per pair
    int sub  = threadIdx.x & 7;
    if (pair >= B) return;

    int i1 = __ldg(t1x + pair);
    int i2 = __ldg(t2x + pair);

    const float4* m1p = (const float4*)(min_tab + (size_t)i1 * 128) + sub;
    const float4* d1p = (const float4*)(dlt_tab + (size_t)i1 * 128) + sub;
    const float4* m2p = (const float4*)(min_tab + (size_t)i2 * 128) + sub;
    const float4* d2p = (const float4*)(dlt_tab + (size_t)i2 * 128) + sub;

    // packed partial products: (even-dim product, odd-dim product)
    u64 P1 = f2_pack(1.0f, 1.0f);
    u64 P2 = P1, PJ = P1, PM = P1;
    float mr = 3.4e38f;   // min raw meet extent over my dims

#pragma unroll
    for (int c = 0; c < 4; c++) {
        // streaming loads: gather data has ~no L1 reuse
        float4 m1 = __ldcs(m1p + c * 8);
        float4 d1 = __ldcs(d1p + c * 8);
        float4 m2 = __ldcs(m2p + c * 8);
        float4 d2 = __ldcs(d2p + c * 8);

#pragma unroll
        for (int h = 0; h < 2; h++) {
            u64 vm1 = h ? f2_pack(m1.z, m1.w) : f2_pack(m1.x, m1.y);
            u64 vd1 = h ? f2_pack(d1.z, d1.w) : f2_pack(d1.x, d1.y);
            u64 vm2 = h ? f2_pack(m2.z, m2.w) : f2_pack(m2.x, m2.y);
            u64 vd2 = h ? f2_pack(d2.z, d2.w) : f2_pack(d2.x, d2.y);

            u64 a2  = f2_fma(vm1, MV2, MM2);   // t1_min
            u64 da2 = f2_fma(vd1, DV2, DM2);   // t1 extent
            u64 c2  = f2_fma(vm2, MV2, MM2);   // t2_min
            u64 dc2 = f2_fma(vd2, DV2, DM2);   // t2 extent
            u64 b2  = f2_add(a2, da2);         // t1_max
            u64 e2  = f2_add(c2, dc2);         // t2_max
            u64 s2  = f2_add(da2, dc2);        // sum of extents

            // scalar min/max (no packed FMNMX)
            float a0, a1, c0, c1, b0, b1, e0, e1;
            f2_unpack(a2, a0, a1);
            f2_unpack(c2, c0, c1);
            f2_unpack(b2, b0, b1);
            f2_unpack(e2, e0, e1);
            u64 jmin2 = f2_pack(fminf(a0, c0), fminf(a1, c1));
            u64 jmax2 = f2_pack(fmaxf(b0, e0), fmaxf(b1, e1));

            u64 ej2 = f2_fma(jmin2, N12, jmax2);   // join extent = jmax - jmin
            u64 em2 = f2_fma(ej2,  N12, s2);       // meet extent = s - ej

            float em0, em1;
            f2_unpack(em2, em0, em1);
            mr = fminf(mr, fminf(em0, em1));

            P1 = f2_mul(P1, da2);
            P2 = f2_mul(P2, dc2);
            PJ = f2_mul(PJ, ej2);
            PM = f2_mul(PM, em2);   // clamp dropped: em<=0 only when
                                    // disjoint, where pm is discarded
        }
    }

    // combine even/odd packed partial products
    float x, y;
    f2_unpack(P1, x, y); float p1 = x * y;
    f2_unpack(P2, x, y); float p2 = x * y;
    f2_unpack(PJ, x, y); float pj = x * y;
    f2_unpack(PM, x, y); float pm = x * y;

    // single per-lane renorm keeps the cross-lane meet product fp32-safe
    int EM = 0;
    pm = split_mant(pm, EM);

    // ratios: outputs only need (meet - t2) and (join - t1) log-differences
    float rm = __fdividef(pm, p2);
    float rj = __fdividef(pj, p1);

    const unsigned int FULL = 0xFFFFFFFFu;
#pragma unroll
    for (int off = 4; off > 0; off >>= 1) {
        rm *= __shfl_xor_sync(FULL, rm, off);
        rj *= __shfl_xor_sync(FULL, rj, off);
        EM += __shfl_xor_sync(FULL, EM, off);
    }

    // disjoint = any lane in my 8-lane group saw em <= 0
    unsigned int ball = __ballot_sync(FULL, mr <= 0.0f);
    bool disjoint = ((ball >> (threadIdx.x & 24)) & 0xFFu) != 0u;

    if (sub == 0) {
        const float LN2 = 0.69314718055994530942f;
        float posv, negv;
        if (disjoint) {
            posv = logf(rj);                       // join_log - t1_log
            negv = 0.0f;
        } else {
            float cond = logf(rm) + (float)EM * LN2;   // log P(t1|t2)
            posv = -cond;
            negv = -logf(fmaxf(1.0f - expf(cond), EPS_F));
        }
        out_pos[pair] = posv;
        out_neg[pair] = negv;
    }
}

extern "C" void kernel_launch(void* const* d_in, const int* in_sizes, int n_in,
                              void* d_out, int out_size) {
    const int*   t1x    = (const int*)d_in[0];
    const int*   t2x    = (const int*)d_in[1];
    const float* min_tb = (const float*)d_in[2];
    const float* dlt_tb = (const float*)d_in[3];

    int B = in_sizes[0];
    float* out_pos = (float*)d_out;
    float* out_neg = (float*)d_out + B;

    // 8 lanes per pair, 32 pairs per 256-thread block
    int pairs_per_block = 32;
    int grid = (B + pairs_per_block - 1) / pairs_per_block;
    box_pair_kernel<<<grid, 256>>>(t1x, t2x, min_tb, dlt_tb, out_pos, out_neg, B);
}

// round 14
// speedup vs baseline: 1.2269x; 1.2269x over previous
#include <cuda_runtime.h>
#include <cuda_bf16.h>
#include <math.h>

// Box-embedding conditional-probability loss. B pairs, D=128.
// R14: revert to R10 — the measured optimum (25.1us, ~94% of the practical
// LTS ceiling: 268MB logical L2->SM traffic at ~10.7 of ~11.3TB/s).
// Verified-dominant design decisions:
//  - 8 lanes/pair, 32 regs, 85% occ (beats all cp.async/deep-MLP variants)
//  - __ldcs streaming gathers (no L1 reuse to protect)
//  - log-volume as product + single mantissa/exponent split (4 logf/pair,
//    not 512 MUFU.LG2)
//  - meet extent via min+max=sum identity; dead clamps removed
//  - ratio reduction: only (meet-t2), (join-t1) log-differences reduced

#define EPS_F 1e-8f

static __device__ __forceinline__ float split_mant(float p, int& e) {
    int ib = __float_as_int(p);
    e += ((ib >> 23) & 0xFF) - 127;
    return __int_as_float((ib & 0x007FFFFF) | 0x3F800000);  // [1,2)
}

__global__ void __launch_bounds__(256, 8)
box_pair_kernel(const int* __restrict__ t1x,
                const int* __restrict__ t2x,
                const float* __restrict__ min_tab,
                const float* __restrict__ dlt_tab,
                float* __restrict__ out_pos,
                float* __restrict__ out_neg,
                int B)
{
    const float MIN_MEAN   = (float)((0.0001 + 0.01) / 2.0);
    const float MIN_VAR    = (float)(0.01 - (0.0001 + 0.01) / 2.0);
    const float DELTA_MEAN = (float)((0.9 + 0.999) / 2.0);
    const float DELTA_VAR  = (float)(0.999 - (0.9 + 0.999) / 2.0);

    int gtid = blockIdx.x * blockDim.x + threadIdx.x;
    int pair = gtid >> 3;           // 8 lanes per pair
    int sub  = threadIdx.x & 7;
    if (pair >= B) return;

    int i1 = __ldg(t1x + pair);
    int i2 = __ldg(t2x + pair);

    const float4* m1p = (const float4*)(min_tab + (size_t)i1 * 128) + sub;
    const float4* d1p = (const float4*)(dlt_tab + (size_t)i1 * 128) + sub;
    const float4* m2p = (const float4*)(min_tab + (size_t)i2 * 128) + sub;
    const float4* d2p = (const float4*)(dlt_tab + (size_t)i2 * 128) + sub;

    float p1 = 1.0f, p2 = 1.0f, pm = 1.0f, pj = 1.0f;
    float mr = 3.4e38f;   // min raw meet extent over my dims

#pragma unroll
    for (int c = 0; c < 4; c++) {
        // streaming loads: gather data has ~1% reuse -> bypass L1 allocation
        float4 m1 = __ldcs(m1p + c * 8);
        float4 d1 = __ldcs(d1p + c * 8);
        float4 m2 = __ldcs(m2p + c * 8);
        float4 d2 = __ldcs(d2p + c * 8);

        const float* m1v = &m1.x;
        const float* d1v = &d1.x;
        const float* m2v = &m2.x;
        const float* d2v = &d2.x;

#pragma unroll
        for (int j = 0; j < 4; j++) {
            float a  = fmaf(m1v[j], MIN_VAR, MIN_MEAN);     // t1_min
            float da = fmaf(d1v[j], DELTA_VAR, DELTA_MEAN); // t1 extent
            float c0 = fmaf(m2v[j], MIN_VAR, MIN_MEAN);     // t2_min
            float dc = fmaf(d2v[j], DELTA_VAR, DELTA_MEAN); // t2 extent
            float b  = a + da;                              // t1_max
            float d  = c0 + dc;                             // t2_max

            float jmin = fminf(a, c0);
            float jmax = fmaxf(b, d);
            float ej   = jmax - jmin;                 // join extent
            float em   = (da + dc) - ej;              // meet extent (identity)

            mr = fminf(mr, em);
            p1 *= da;
            p2 *= dc;
            pj *= ej;
            pm *= em;   // clamp dropped: em<=0 only when disjoint, where
                        // pm is discarded by the output branch
        }
    }

    // single per-lane renorm keeps the cross-lane meet product fp32-safe
    int EM = 0;
    pm = split_mant(pm, EM);

    // ratios: outputs only need (meet - t2) and (join - t1) log-differences
    float rm = __fdividef(pm, p2);
    float rj = __fdividef(pj, p1);

    const unsigned int FULL = 0xFFFFFFFFu;
#pragma unroll
    for (int off = 4; off > 0; off >>= 1) {
        rm *= __shfl_xor_sync(FULL, rm, off);
        rj *= __shfl_xor_sync(FULL, rj, off);
        EM += __shfl_xor_sync(FULL, EM, off);
    }

    // disjoint = any lane in my 8-lane group saw em <= 0
    unsigned int ball = __ballot_sync(FULL, mr <= 0.0f);
    bool disjoint = ((ball >> (threadIdx.x & 24)) & 0xFFu) != 0u;

    if (sub == 0) {
        const float LN2 = 0.69314718055994530942f;
        float posv, negv;
        if (disjoint) {
            posv = logf(rj);                       // join_log - t1_log
            negv = 0.0f;
        } else {
            float cond = logf(rm) + (float)EM * LN2;   // log P(t1|t2)
            posv = -cond;
            negv = -logf(fmaxf(1.0f - expf(cond), EPS_F));
        }
        out_pos[pair] = posv;
        out_neg[pair] = negv;
    }
}

extern "C" void kernel_launch(void* const* d_in, const int* in_sizes, int n_in,
                              void* d_out, int out_size) {
    const int*   t1x    = (const int*)d_in[0];
    const int*   t2x    = (const int*)d_in[1];
    const float* min_tb = (const float*)d_in[2];
    const float* dlt_tb = (const float*)d_in[3];

    int B = in_sizes[0];
    float* out_pos = (float*)d_out;
    float* out_neg = (float*)d_out + B;

    // 8 lanes per pair, 32 pairs per 256-thread block
    int pairs_per_block = 32;
    int grid = (B + pairs_per_block - 1) / pairs_per_block;
    box_pair_kernel<<<grid, 256>>>(t1x, t2x, min_tb, dlt_tb, out_pos, out_neg, B);
}

// round 15
// speedup vs baseline: 1.2746x; 1.0389x over previous
#include <cuda_runtime.h>
#include <cuda_bf16.h>
#include <math.h>

// Box-embedding conditional-probability loss. B pairs, D=128.
// FINAL (R10 configuration — measured optimum, ~94% of the practical LTS
// ceiling; identical-source rebench spread is +/-2us, so this is converged).
// Verified-dominant design decisions:
//  - 8 lanes/pair, 32 regs (__launch_bounds__(256,8)), ~full occupancy
//    (beats all cp.async pipeline and register-MLP variants, R5-R13)
//  - __ldcs streaming gathers: gather rows have no exploitable L1 reuse
//  - log-volume as running product + one mantissa/exponent split
//    (4 logf/pair instead of 512 MUFU.LG2)
//  - meet extent via the min+max=sum identity (removes 2 FMNMX/dim)
//  - dead clamps removed (extents ~0.95 >> 1e-8; meet clamp only binds
//    in the disjoint branch where the product is discarded)
//  - ratio reduction: reduce only (meet-t2) and (join-t1) log-differences

#define EPS_F 1e-8f

static __device__ __forceinline__ float split_mant(float p, int& e) {
    int ib = __float_as_int(p);
    e += ((ib >> 23) & 0xFF) - 127;
    return __int_as_float((ib & 0x007FFFFF) | 0x3F800000);  // [1,2)
}

__global__ void __launch_bounds__(256, 8)
box_pair_kernel(const int* __restrict__ t1x,
                const int* __restrict__ t2x,
                const float* __restrict__ min_tab,
                const float* __restrict__ dlt_tab,
                float* __restrict__ out_pos,
                float* __restrict__ out_neg,
                int B)
{
    const float MIN_MEAN   = (float)((0.0001 + 0.01) / 2.0);
    const float MIN_VAR    = (float)(0.01 - (0.0001 + 0.01) / 2.0);
    const float DELTA_MEAN = (float)((0.9 + 0.999) / 2.0);
    const float DELTA_VAR  = (float)(0.999 - (0.9 + 0.999) / 2.0);

    int gtid = blockIdx.x * blockDim.x + threadIdx.x;
    int pair = gtid >> 3;           // 8 lanes per pair
    int sub  = threadIdx.x & 7;
    if (pair >= B) return;

    int i1 = __ldg(t1x + pair);
    int i2 = __ldg(t2x + pair);

    const float4* m1p = (const float4*)(min_tab + (size_t)i1 * 128) + sub;
    const float4* d1p = (const float4*)(dlt_tab + (size_t)i1 * 128) + sub;
    const float4* m2p = (const float4*)(min_tab + (size_t)i2 * 128) + sub;
    const float4* d2p = (const float4*)(dlt_tab + (size_t)i2 * 128) + sub;

    float p1 = 1.0f, p2 = 1.0f, pm = 1.0f, pj = 1.0f;
    float mr = 3.4e38f;   // min raw meet extent over my dims

#pragma unroll
    for (int c = 0; c < 4; c++) {
        // streaming loads: bypass L1 allocation for zero-reuse gather data
        float4 m1 = __ldcs(m1p + c * 8);
        float4 d1 = __ldcs(d1p + c * 8);
        float4 m2 = __ldcs(m2p + c * 8);
        float4 d2 = __ldcs(d2p + c * 8);

        const float* m1v = &m1.x;
        const float* d1v = &d1.x;
        const float* m2v = &m2.x;
        const float* d2v = &d2.x;

#pragma unroll
        for (int j = 0; j < 4; j++) {
            float a  = fmaf(m1v[j], MIN_VAR, MIN_MEAN);     // t1_min
            float da = fmaf(d1v[j], DELTA_VAR, DELTA_MEAN); // t1 extent
            float c0 = fmaf(m2v[j], MIN_VAR, MIN_MEAN);     // t2_min
            float dc = fmaf(d2v[j], DELTA_VAR, DELTA_MEAN); // t2 extent
            float b  = a + da;                              // t1_max
            float d  = c0 + dc;                             // t2_max

            float jmin = fminf(a, c0);
            float jmax = fmaxf(b, d);
            float ej   = jmax - jmin;                 // join extent
            float em   = (da + dc) - ej;              // meet extent (identity)

            mr = fminf(mr, em);
            p1 *= da;
            p2 *= dc;
            pj *= ej;
            pm *= em;   // clamp dropped: em<=0 only when disjoint, where
                        // pm is discarded by the output branch
        }
    }

    // single per-lane renorm keeps the cross-lane meet product fp32-safe
    int EM = 0;
    pm = split_mant(pm, EM);

    // ratios: outputs only need (meet - t2) and (join - t1) log-differences
    float rm = __fdividef(pm, p2);
    float rj = __fdividef(pj, p1);

    const unsigned int FULL = 0xFFFFFFFFu;
#pragma unroll
    for (int off = 4; off > 0; off >>= 1) {
        rm *= __shfl_xor_sync(FULL, rm, off);
        rj *= __shfl_xor_sync(FULL, rj, off);
        EM += __shfl_xor_sync(FULL, EM, off);
    }

    // disjoint = any lane in my 8-lane group saw em <= 0
    unsigned int ball = __ballot_sync(FULL, mr <= 0.0f);
    bool disjoint = ((ball >> (threadIdx.x & 24)) & 0xFFu) != 0u;

    if (sub == 0) {
        const float LN2 = 0.69314718055994530942f;
        float posv, negv;
        if (disjoint) {
            posv = logf(rj);                       // join_log - t1_log
            negv = 0.0f;
        } else {
            float cond = logf(rm) + (float)EM * LN2;   // log P(t1|t2)
            posv = -cond;
            negv = -logf(fmaxf(1.0f - expf(cond), EPS_F));
        }
        out_pos[pair] = posv;
        out_neg[pair] = negv;
    }
}

extern "C" void kernel_launch(void* const* d_in, const int* in_sizes, int n_in,
                              void* d_out, int out_size) {
    const int*   t1x    = (const int*)d_in[0];
    const int*   t2x    = (const int*)d_in[1];
    const float* min_tb = (const float*)d_in[2];
    const float* dlt_tb = (const float*)d_in[3];

    int B = in_sizes[0];
    float* out_pos = (float*)d_out;
    float* out_neg = (float*)d_out + B;

    // 8 lanes per pair, 32 pairs per 256-thread block
    int pairs_per_block = 32;
    int grid = (B + pairs_per_block - 1) / pairs_per_block;
    box_pair_kernel<<<grid, 256>>>(t1x, t2x, min_tb, dlt_tb, out_pos, out_neg, B);
}

// round 16
// speedup vs baseline: 1.3397x; 1.0511x over previous
#include <cuda_runtime.h>
#include <cuda_bf16.h>
#include <math.h>

// Box-embedding conditional-probability loss. B pairs, D=128.
// R16: R10 frame (measured optimum, ~94% of practical LTS ceiling) minus
// the exponent-split machinery. Range analysis: extents = 0.9495+-0.0495,
// meet extents ~0.9, so the 128-dim meet product >= ~3e-17 — four decades
// above fp32 underflow. split_mant + EM reduction (3 SHFL + 3 IADD + split
// + epilogue term) are dead weight; removed.
// Retained verified-dominant decisions:
//  - 8 lanes/pair, 32 regs (__launch_bounds__(256,8)), ~full occupancy
//  - __ldcs streaming gathers (no exploitable L1 reuse)
//  - log-volume as running product (4 logf/pair, not 512 MUFU.LG2)
//  - meet extent via min+max=sum identity; dead clamps removed
//  - ratio reduction: only (meet-t2) and (join-t1) log-differences reduced

#define EPS_F 1e-8f

__global__ void __launch_bounds__(256, 8)
box_pair_kernel(const int* __restrict__ t1x,
                const int* __restrict__ t2x,
                const float* __restrict__ min_tab,
                const float* __restrict__ dlt_tab,
                float* __restrict__ out_pos,
                float* __restrict__ out_neg,
                int B)
{
    const float MIN_MEAN   = (float)((0.0001 + 0.01) / 2.0);
    const float MIN_VAR    = (float)(0.01 - (0.0001 + 0.01) / 2.0);
    const float DELTA_MEAN = (float)((0.9 + 0.999) / 2.0);
    const float DELTA_VAR  = (float)(0.999 - (0.9 + 0.999) / 2.0);

    int gtid = blockIdx.x * blockDim.x + threadIdx.x;
    int pair = gtid >> 3;           // 8 lanes per pair
    int sub  = threadIdx.x & 7;
    if (pair >= B) return;

    int i1 = __ldg(t1x + pair);
    int i2 = __ldg(t2x + pair);

    const float4* m1p = (const float4*)(min_tab + (size_t)i1 * 128) + sub;
    const float4* d1p = (const float4*)(dlt_tab + (size_t)i1 * 128) + sub;
    const float4* m2p = (const float4*)(min_tab + (size_t)i2 * 128) + sub;
    const float4* d2p = (const float4*)(dlt_tab + (size_t)i2 * 128) + sub;

    float p1 = 1.0f, p2 = 1.0f, pm = 1.0f, pj = 1.0f;
    float mr = 3.4e38f;   // min raw meet extent over my dims

#pragma unroll
    for (int c = 0; c < 4; c++) {
        // streaming loads: bypass L1 allocation for zero-reuse gather data
        float4 m1 = __ldcs(m1p + c * 8);
        float4 d1 = __ldcs(d1p + c * 8);
        float4 m2 = __ldcs(m2p + c * 8);
        float4 d2 = __ldcs(d2p + c * 8);

        const float* m1v = &m1.x;
        const float* d1v = &d1.x;
        const float* m2v = &m2.x;
        const float* d2v = &d2.x;

#pragma unroll
        for (int j = 0; j < 4; j++) {
            float a  = fmaf(m1v[j], MIN_VAR, MIN_MEAN);     // t1_min
            float da = fmaf(d1v[j], DELTA_VAR, DELTA_MEAN); // t1 extent
            float c0 = fmaf(m2v[j], MIN_VAR, MIN_MEAN);     // t2_min
            float dc = fmaf(d2v[j], DELTA_VAR, DELTA_MEAN); // t2 extent
            float b  = a + da;                              // t1_max
            float d  = c0 + dc;                             // t2_max

            float jmin = fminf(a, c0);
            float jmax = fmaxf(b, d);
            float ej   = jmax - jmin;                 // join extent
            float em   = (da + dc) - ej;              // meet extent (identity)

            mr = fminf(mr, em);
            p1 *= da;
            p2 *= dc;
            pj *= ej;
            pm *= em;   // clamp dropped: em<=0 only when disjoint, where
                        // pm is discarded by the output branch
        }
    }

    // ratios: outputs only need (meet - t2) and (join - t1) log-differences.
    // All products are fp32-safe: extents 0.9495+-0.0495 -> per-lane
    // products in [0.2, 2], 8-lane ratio products in [1e-4, 3e3].
    float rm = __fdividef(pm, p2);
    float rj = __fdividef(pj, p1);

    const unsigned int FULL = 0xFFFFFFFFu;
#pragma unroll
    for (int off = 4; off > 0; off >>= 1) {
        rm *= __shfl_xor_sync(FULL, rm, off);
        rj *= __shfl_xor_sync(FULL, rj, off);
    }

    // disjoint = any lane in my 8-lane group saw em <= 0
    unsigned int ball = __ballot_sync(FULL, mr <= 0.0f);
    bool disjoint = ((ball >> (threadIdx.x & 24)) & 0xFFu) != 0u;

    if (sub == 0) {
        float posv, negv;
        if (disjoint) {
            posv = logf(rj);                       // join_log - t1_log
            negv = 0.0f;
        } else {
            float cond = logf(rm);                 // log P(t1|t2)
            posv = -cond;
            negv = -logf(fmaxf(1.0f - rm, EPS_F)); // 1 - exp(cond) = 1 - rm
        }
        out_pos[pair] = posv;
        out_neg[pair] = negv;
    }
}

extern "C" void kernel_launch(void* const* d_in, const int* in_sizes, int n_in,
                              void* d_out, int out_size) {
    const int*   t1x    = (const int*)d_in[0];
    const int*   t2x    = (const int*)d_in[1];
    const float* min_tb = (const float*)d_in[2];
    const float* dlt_tb = (const float*)d_in[3];

    int B = in_sizes[0];
    float* out_pos = (float*)d_out;
    float* out_neg = (float*)d_out + B;

    // 8 lanes per pair, 32 pairs per 256-thread block
    int pairs_per_block = 32;
    int grid = (B + pairs_per_block - 1) / pairs_per_block;
    box_pair_kernel<<<grid, 256>>>(t1x, t2x, min_tb, dlt_tb, out_pos, out_neg, B);
}